// round 7
// baseline (speedup 1.0000x reference)
#include <cuda_runtime.h>
#include <cuda_fp16.h>
#include <mma.h>
#include <math.h>
#include <stdint.h>

using namespace nvcuda;

#define NN 100000
#define EE 1600000
#define NEG 0.01f

// ---------------- scratch (device globals) ---------------------------------
__device__ __half2 g_h[NN * 32];     // h' = dinv*(in@W), fp16 gather buffer
__device__ __half2 g_bufA[NN * 32];  // fp16 node features (ping)
__device__ __half2 g_bufB[NN * 32];  // fp16 node features (pong)
__device__ int   g_cnt[NN];          // zero at entry of every call (invariant)
__device__ int   g_rowptr[NN];
__device__ int   g_pos[NN];
__device__ int   g_col[EE];
__device__ float g_dinv[NN];
__device__ int   g_bsum[128];

// ---------------- CSR build ------------------------------------------------
__global__ void k_hist(const int* __restrict__ dst) {
    int t = blockIdx.x * blockDim.x + threadIdx.x;
    if (t * 4 < EE) {
        int4 d = __ldg((const int4*)dst + t);
        atomicAdd(&g_cnt[d.x], 1);
        atomicAdd(&g_cnt[d.y], 1);
        atomicAdd(&g_cnt[d.z], 1);
        atomicAdd(&g_cnt[d.w], 1);
    }
}

__global__ void k_scanA() {
    __shared__ int s[1024];
    int tid = threadIdx.x;
    int i = blockIdx.x * 1024 + tid;
    int v = (i < NN) ? g_cnt[i] : 0;
    if (i < NN) g_dinv[i] = rsqrtf((float)(v + 1));
    s[tid] = v;
    __syncthreads();
    #pragma unroll
    for (int off = 1; off < 1024; off <<= 1) {
        int t = (tid >= off) ? s[tid - off] : 0;
        __syncthreads();
        s[tid] += t;
        __syncthreads();
    }
    if (i < NN) g_rowptr[i] = s[tid] - v;
    if (tid == 1023) g_bsum[blockIdx.x] = s[1023];
}

__global__ void k_scanB(int nb) {
    int lane = threadIdx.x;
    int base = lane * 4;
    int v0 = (base + 0 < nb) ? g_bsum[base + 0] : 0;
    int v1 = (base + 1 < nb) ? g_bsum[base + 1] : 0;
    int v2 = (base + 2 < nb) ? g_bsum[base + 2] : 0;
    int v3 = (base + 3 < nb) ? g_bsum[base + 3] : 0;
    int s1 = v0 + v1, s2 = s1 + v2, s3 = s2 + v3;
    int tot = s3;
    int run = tot;
    #pragma unroll
    for (int off = 1; off < 32; off <<= 1) {
        int t = __shfl_up_sync(0xffffffffu, run, off);
        if (lane >= off) run += t;
    }
    int excl = run - tot;
    if (base + 0 < nb) g_bsum[base + 0] = excl;
    if (base + 1 < nb) g_bsum[base + 1] = excl + v0;
    if (base + 2 < nb) g_bsum[base + 2] = excl + s1;
    if (base + 3 < nb) g_bsum[base + 3] = excl + s2;
}

__global__ void k_scanC() {
    int i = blockIdx.x * blockDim.x + threadIdx.x;
    if (i < NN) {
        int rp = g_rowptr[i] + g_bsum[i >> 10];
        g_rowptr[i] = rp;
        g_pos[i] = rp;
    }
}

__global__ void k_scatter(const int* __restrict__ src, const int* __restrict__ dst) {
    int t = blockIdx.x * blockDim.x + threadIdx.x;
    if (t * 4 < EE) {
        int4 d = __ldg((const int4*)dst + t);
        int4 s = __ldg((const int4*)src + t);
        int p0 = atomicAdd(&g_pos[d.x], 1);
        int p1 = atomicAdd(&g_pos[d.y], 1);
        int p2 = atomicAdd(&g_pos[d.z], 1);
        int p3 = atomicAdd(&g_pos[d.w], 1);
        g_col[p0] = s.x;
        g_col[p1] = s.y;
        g_col[p2] = s.z;
        g_col[p3] = s.w;
    }
}

// ---------------- WMMA GEMM: h'[N,64](fp16) = dinv[row]*(in @ W) -----------
template<bool F32IN>
__global__ void __launch_bounds__(256) k_gemm_wmma(
    const void* __restrict__ inv, const float* __restrict__ W,
    __half2* __restrict__ out) {
    __shared__ __align__(16) char sraw[24576];
    half* As = (half*)sraw;             // 128 x 64
    half* Bs = (half*)(sraw + 16384);   // 64 x 64
    int tid  = threadIdx.x;
    int warp = tid >> 5, lane = tid & 31;
    int rowbase = blockIdx.x * 128;

    #pragma unroll
    for (int k = 0; k < 4; k++) {
        int i = tid + k * 256;
        float4 w = __ldg((const float4*)W + i);
        __half2 h0 = __floats2half2_rn(w.x, w.y);
        __half2 h1 = __floats2half2_rn(w.z, w.w);
        *(uint2*)(Bs + i * 4) = make_uint2(*(uint32_t*)&h0, *(uint32_t*)&h1);
    }
    if (F32IN) {
        const float4* in4 = (const float4*)inv;
        #pragma unroll
        for (int k = 0; k < 8; k++) {
            int i = tid + k * 256;
            int row = i >> 4, q = i & 15;
            int gr = rowbase + row;
            float4 v = (gr < NN) ? __ldg(in4 + (size_t)gr * 16 + q) : make_float4(0, 0, 0, 0);
            __half2 h0 = __floats2half2_rn(v.x, v.y);
            __half2 h1 = __floats2half2_rn(v.z, v.w);
            *(uint2*)(As + row * 64 + q * 4) =
                make_uint2(*(uint32_t*)&h0, *(uint32_t*)&h1);
        }
    } else {
        const uint4* in4 = (const uint4*)inv;
        #pragma unroll
        for (int k = 0; k < 4; k++) {
            int i = tid + k * 256;
            int row = i >> 3, q = i & 7;
            int gr = rowbase + row;
            uint4 v = (gr < NN) ? __ldg(in4 + (size_t)gr * 8 + q) : make_uint4(0, 0, 0, 0);
            *(uint4*)(As + row * 64 + q * 8) = v;
        }
    }
    __syncthreads();

    wmma::fragment<wmma::accumulator, 16, 16, 16, float> c[4];
    #pragma unroll
    for (int nt = 0; nt < 4; nt++) wmma::fill_fragment(c[nt], 0.0f);
    const half* arow = As + warp * 16 * 64;
    #pragma unroll
    for (int k0 = 0; k0 < 64; k0 += 16) {
        wmma::fragment<wmma::matrix_a, 16, 16, 16, half, wmma::row_major> a;
        wmma::load_matrix_sync(a, arow + k0, 64);
        #pragma unroll
        for (int nt = 0; nt < 4; nt++) {
            wmma::fragment<wmma::matrix_b, 16, 16, 16, half, wmma::row_major> b;
            wmma::load_matrix_sync(b, Bs + k0 * 64 + nt * 16, 64);
            wmma::mma_sync(c[nt], a, b, c[nt]);
        }
    }
    __syncthreads();

    float* Cst = (float*)sraw + warp * 256;
    int r = lane >> 1;
    int chalf = (lane & 1) * 8;
    int grow = rowbase + warp * 16 + r;
    float di = (grow < NN) ? g_dinv[grow] : 0.f;
    #pragma unroll
    for (int nt = 0; nt < 4; nt++) {
        wmma::store_matrix_sync(Cst, c[nt], 16, wmma::mem_row_major);
        __syncwarp();
        if (grow < NN) {
            float4 v0 = *(const float4*)(Cst + r * 16 + chalf);
            float4 v1 = *(const float4*)(Cst + r * 16 + chalf + 4);
            __half2 h0 = __floats2half2_rn(di * v0.x, di * v0.y);
            __half2 h1 = __floats2half2_rn(di * v0.z, di * v0.w);
            __half2 h2 = __floats2half2_rn(di * v1.x, di * v1.y);
            __half2 h3 = __floats2half2_rn(di * v1.z, di * v1.w);
            *(uint4*)(out + (size_t)grow * 32 + nt * 8 + (lane & 1) * 4) =
                make_uint4(*(uint32_t*)&h0, *(uint32_t*)&h1,
                           *(uint32_t*)&h2, *(uint32_t*)&h3);
        }
        __syncwarp();
    }
}

// ---------------- Aggregation: warp-per-row, pipelined gather --------------
// HALF_OUT: write fp16 features (intermediate); else fp32 (final output).
// ZERO_CNT: final layer restores g_cnt==0 invariant for next graph replay.
template<bool HALF_OUT, bool ZERO_CNT>
__global__ void k_agg(const __half2* __restrict__ h, const float* __restrict__ bias,
                      void* __restrict__ outv) {
    int wid  = (blockIdx.x * blockDim.x + threadIdx.x) >> 5;
    int lane = threadIdx.x & 31;
    if (wid >= NN) return;
    int start = g_rowptr[wid];
    int cnt   = g_cnt[wid];
    if (ZERO_CNT && lane == 0) g_cnt[wid] = 0;   // warp program order: read precedes write
    float di  = g_dinv[wid];
    const int* cp = g_col + start;

    float a0 = 0.f, a1 = 0.f;
    int nfull = cnt >> 3;
    if (nfull) {
        int i0 = __ldg(cp + 0), i1 = __ldg(cp + 1), i2 = __ldg(cp + 2), i3 = __ldg(cp + 3);
        int i4 = __ldg(cp + 4), i5 = __ldg(cp + 5), i6 = __ldg(cp + 6), i7 = __ldg(cp + 7);
        for (int b = 1; b < nfull; b++) {
            // gathers for the current batch
            __half2 v0 = __ldg(h + (size_t)i0 * 32 + lane);
            __half2 v1 = __ldg(h + (size_t)i1 * 32 + lane);
            __half2 v2 = __ldg(h + (size_t)i2 * 32 + lane);
            __half2 v3 = __ldg(h + (size_t)i3 * 32 + lane);
            __half2 v4 = __ldg(h + (size_t)i4 * 32 + lane);
            __half2 v5 = __ldg(h + (size_t)i5 * 32 + lane);
            __half2 v6 = __ldg(h + (size_t)i6 * 32 + lane);
            __half2 v7 = __ldg(h + (size_t)i7 * 32 + lane);
            // prefetch next batch's indices (overlaps gather latency)
            const int* nx = cp + b * 8;
            i0 = __ldg(nx + 0); i1 = __ldg(nx + 1); i2 = __ldg(nx + 2); i3 = __ldg(nx + 3);
            i4 = __ldg(nx + 4); i5 = __ldg(nx + 5); i6 = __ldg(nx + 6); i7 = __ldg(nx + 7);
            float2 f0 = __half22float2(v0), f1 = __half22float2(v1);
            float2 f2 = __half22float2(v2), f3 = __half22float2(v3);
            float2 f4 = __half22float2(v4), f5 = __half22float2(v5);
            float2 f6 = __half22float2(v6), f7 = __half22float2(v7);
            a0 += f0.x + f1.x + f2.x + f3.x + f4.x + f5.x + f6.x + f7.x;
            a1 += f0.y + f1.y + f2.y + f3.y + f4.y + f5.y + f6.y + f7.y;
        }
        {   // drain last full batch
            __half2 v0 = __ldg(h + (size_t)i0 * 32 + lane);
            __half2 v1 = __ldg(h + (size_t)i1 * 32 + lane);
            __half2 v2 = __ldg(h + (size_t)i2 * 32 + lane);
            __half2 v3 = __ldg(h + (size_t)i3 * 32 + lane);
            __half2 v4 = __ldg(h + (size_t)i4 * 32 + lane);
            __half2 v5 = __ldg(h + (size_t)i5 * 32 + lane);
            __half2 v6 = __ldg(h + (size_t)i6 * 32 + lane);
            __half2 v7 = __ldg(h + (size_t)i7 * 32 + lane);
            float2 f0 = __half22float2(v0), f1 = __half22float2(v1);
            float2 f2 = __half22float2(v2), f3 = __half22float2(v3);
            float2 f4 = __half22float2(v4), f5 = __half22float2(v5);
            float2 f6 = __half22float2(v6), f7 = __half22float2(v7);
            a0 += f0.x + f1.x + f2.x + f3.x + f4.x + f5.x + f6.x + f7.x;
            a1 += f0.y + f1.y + f2.y + f3.y + f4.y + f5.y + f6.y + f7.y;
        }
    }
    int j = nfull * 8;
    if (cnt - j >= 4) {
        int s0 = __ldg(cp + j + 0), s1 = __ldg(cp + j + 1);
        int s2 = __ldg(cp + j + 2), s3 = __ldg(cp + j + 3);
        float2 f0 = __half22float2(__ldg(h + (size_t)s0 * 32 + lane));
        float2 f1 = __half22float2(__ldg(h + (size_t)s1 * 32 + lane));
        float2 f2 = __half22float2(__ldg(h + (size_t)s2 * 32 + lane));
        float2 f3 = __half22float2(__ldg(h + (size_t)s3 * 32 + lane));
        a0 += f0.x + f1.x + f2.x + f3.x;
        a1 += f0.y + f1.y + f2.y + f3.y;
        j += 4;
    }
    for (; j < cnt; j++) {
        int s = __ldg(cp + j);
        float2 f = __half22float2(__ldg(h + (size_t)s * 32 + lane));
        a0 += f.x; a1 += f.y;
    }

    float2 hs = __half22float2(__ldg(h + (size_t)wid * 32 + lane));
    float2 bb = __ldg((const float2*)bias + lane);
    float o0 = di * (a0 + hs.x) + bb.x;
    float o1 = di * (a1 + hs.y) + bb.y;
    o0 = (o0 >= 0.f) ? o0 : NEG * o0;
    o1 = (o1 >= 0.f) ? o1 : NEG * o1;
    if (HALF_OUT) {
        ((__half2*)outv)[(size_t)wid * 32 + lane] = __floats2half2_rn(o0, o1);
    } else {
        float2 oo; oo.x = o0; oo.y = o1;
        ((float2*)outv)[(size_t)wid * 32 + lane] = oo;
    }
}

// ---------------- launch ----------------------------------------------------
extern "C" void kernel_launch(void* const* d_in, const int* in_sizes, int n_in,
                              void* d_out, int out_size) {
    (void)in_sizes; (void)n_in; (void)out_size;
    const float* x  = (const float*)d_in[0];
    const int*   ei = (const int*)d_in[1];
    const int* src = ei;
    const int* dst = ei + EE;
    const float* Wt[4] = { (const float*)d_in[2], (const float*)d_in[4],
                           (const float*)d_in[6], (const float*)d_in[8] };
    const float* bt[4] = { (const float*)d_in[3], (const float*)d_in[5],
                           (const float*)d_in[7], (const float*)d_in[9] };

    __half2 *p_h, *p_a, *p_b;
    cudaGetSymbolAddress((void**)&p_h, g_h);
    cudaGetSymbolAddress((void**)&p_a, g_bufA);
    cudaGetSymbolAddress((void**)&p_b, g_bufB);

    const int NB_SCAN = (NN + 1023) / 1024;    // 98
    const int NB_N256 = (NN + 255) / 256;      // 391
    const int NB_E4   = (EE / 4 + 255) / 256;  // 1563

    // CSR build — g_cnt==0 at entry (module init / restored by final k_agg)
    k_hist<<<NB_E4, 256>>>(dst);
    k_scanA<<<NB_SCAN, 1024>>>();
    k_scanB<<<1, 32>>>(NB_SCAN);
    k_scanC<<<NB_N256, 256>>>();
    k_scatter<<<NB_E4, 256>>>(src, dst);

    const int GEMM_BLOCKS = (NN + 127) / 128;  // 782
    const int AGG_BLOCKS  = (NN * 32 + 511) / 512;  // 6250 (512 thr, 16 warps)

    // layer 1
    k_gemm_wmma<true ><<<GEMM_BLOCKS, 256>>>(x,   Wt[0], p_h);
    k_agg<true , false><<<AGG_BLOCKS, 512>>>(p_h, bt[0], p_a);
    // layer 2
    k_gemm_wmma<false><<<GEMM_BLOCKS, 256>>>(p_a, Wt[1], p_h);
    k_agg<true , false><<<AGG_BLOCKS, 512>>>(p_h, bt[1], p_b);
    // layer 3
    k_gemm_wmma<false><<<GEMM_BLOCKS, 256>>>(p_b, Wt[2], p_h);
    k_agg<true , false><<<AGG_BLOCKS, 512>>>(p_h, bt[2], p_a);
    // layer 4 (final: fp32 out, restore g_cnt invariant)
    k_gemm_wmma<false><<<GEMM_BLOCKS, 256>>>(p_a, Wt[3], p_h);
    k_agg<false, true ><<<AGG_BLOCKS, 512>>>(p_h, bt[3], d_out);
}

// round 8
// speedup vs baseline: 1.0357x; 1.0357x over previous
#include <cuda_runtime.h>
#include <cuda_fp16.h>
#include <mma.h>
#include <math.h>
#include <stdint.h>

using namespace nvcuda;

#define NN 100000
#define EE 1600000
#define NEG 0.01f

// ---------------- scratch (device globals) ---------------------------------
__device__ __half2 g_h[NN * 32];     // h' = dinv*(in@W), fp16 gather buffer
__device__ __half2 g_bufA[NN * 32];  // fp16 node features (ping)
__device__ __half2 g_bufB[NN * 32];  // fp16 node features (pong)
__device__ int   g_cnt[NN];          // ==0 at entry of every call (invariant)
__device__ int   g_rowptr[NN];
__device__ int   g_pos[NN];
__device__ int   g_col[EE];
__device__ float g_dinv[NN];
__device__ int   g_bsum[128];

// ---------------- CSR build ------------------------------------------------
__global__ void k_hist(const int* __restrict__ dst) {
    int t = blockIdx.x * blockDim.x + threadIdx.x;
    if (t * 4 < EE) {
        int4 d = ((const int4*)dst)[t];
        atomicAdd(&g_cnt[d.x], 1);
        atomicAdd(&g_cnt[d.y], 1);
        atomicAdd(&g_cnt[d.z], 1);
        atomicAdd(&g_cnt[d.w], 1);
    }
}

__global__ void k_scanA() {
    __shared__ int s[1024];
    int tid = threadIdx.x;
    int i = blockIdx.x * 1024 + tid;
    int v = (i < NN) ? g_cnt[i] : 0;
    if (i < NN) g_dinv[i] = rsqrtf((float)(v + 1));
    s[tid] = v;
    __syncthreads();
    #pragma unroll
    for (int off = 1; off < 1024; off <<= 1) {
        int t = (tid >= off) ? s[tid - off] : 0;
        __syncthreads();
        s[tid] += t;
        __syncthreads();
    }
    if (i < NN) g_rowptr[i] = s[tid] - v;
    if (tid == 1023) g_bsum[blockIdx.x] = s[1023];
}

__global__ void k_scanB(int nb) {
    int lane = threadIdx.x;
    int base = lane * 4;
    int v0 = (base + 0 < nb) ? g_bsum[base + 0] : 0;
    int v1 = (base + 1 < nb) ? g_bsum[base + 1] : 0;
    int v2 = (base + 2 < nb) ? g_bsum[base + 2] : 0;
    int v3 = (base + 3 < nb) ? g_bsum[base + 3] : 0;
    int s1 = v0 + v1, s2 = s1 + v2, s3 = s2 + v3;
    int tot = s3;
    int run = tot;
    #pragma unroll
    for (int off = 1; off < 32; off <<= 1) {
        int t = __shfl_up_sync(0xffffffffu, run, off);
        if (lane >= off) run += t;
    }
    int excl = run - tot;
    if (base + 0 < nb) g_bsum[base + 0] = excl;
    if (base + 1 < nb) g_bsum[base + 1] = excl + v0;
    if (base + 2 < nb) g_bsum[base + 2] = excl + s1;
    if (base + 3 < nb) g_bsum[base + 3] = excl + s2;
}

__global__ void k_scanC() {
    int i = blockIdx.x * blockDim.x + threadIdx.x;
    if (i < NN) {
        int rp = g_rowptr[i] + g_bsum[i >> 10];
        g_rowptr[i] = rp;
        g_pos[i] = rp;
    }
}

__global__ void k_scatter(const int* __restrict__ src, const int* __restrict__ dst) {
    int t = blockIdx.x * blockDim.x + threadIdx.x;
    if (t * 4 < EE) {
        int4 d = ((const int4*)dst)[t];
        int4 s = ((const int4*)src)[t];
        int p0 = atomicAdd(&g_pos[d.x], 1);
        int p1 = atomicAdd(&g_pos[d.y], 1);
        int p2 = atomicAdd(&g_pos[d.z], 1);
        int p3 = atomicAdd(&g_pos[d.w], 1);
        g_col[p0] = s.x;
        g_col[p1] = s.y;
        g_col[p2] = s.z;
        g_col[p3] = s.w;
    }
}

// ---------------- WMMA GEMM: h'[N,64](fp16) = dinv[row]*(in @ W) -----------
// 256 threads (8 warps), 128 rows/block. Each warp: 16-row strip, 4 n-tiles.
template<bool F32IN>
__global__ void __launch_bounds__(256) k_gemm_wmma(
    const void* __restrict__ inv, const float* __restrict__ W,
    __half2* __restrict__ out) {
    __shared__ __align__(16) char sraw[24576];
    half* As = (half*)sraw;             // 128 x 64 (ldm 64)
    half* Bs = (half*)(sraw + 16384);   // 64 x 64  (ldm 64)
    int tid  = threadIdx.x;
    int warp = tid >> 5, lane = tid & 31;
    int rowbase = blockIdx.x * 128;

    #pragma unroll
    for (int k = 0; k < 4; k++) {
        int i = tid + k * 256;
        float4 w = ((const float4*)W)[i];
        __half2 h0 = __floats2half2_rn(w.x, w.y);
        __half2 h1 = __floats2half2_rn(w.z, w.w);
        *(uint2*)(Bs + i * 4) = make_uint2(*(uint32_t*)&h0, *(uint32_t*)&h1);
    }
    if (F32IN) {
        const float4* in4 = (const float4*)inv;
        #pragma unroll
        for (int k = 0; k < 8; k++) {
            int i = tid + k * 256;
            int row = i >> 4, q = i & 15;
            int gr = rowbase + row;
            float4 v = (gr < NN) ? in4[(size_t)gr * 16 + q] : make_float4(0, 0, 0, 0);
            __half2 h0 = __floats2half2_rn(v.x, v.y);
            __half2 h1 = __floats2half2_rn(v.z, v.w);
            *(uint2*)(As + row * 64 + q * 4) =
                make_uint2(*(uint32_t*)&h0, *(uint32_t*)&h1);
        }
    } else {
        const uint4* in4 = (const uint4*)inv;
        #pragma unroll
        for (int k = 0; k < 4; k++) {
            int i = tid + k * 256;
            int row = i >> 3, q = i & 7;
            int gr = rowbase + row;
            uint4 v = (gr < NN) ? in4[(size_t)gr * 8 + q] : make_uint4(0, 0, 0, 0);
            *(uint4*)(As + row * 64 + q * 8) = v;
        }
    }
    __syncthreads();

    wmma::fragment<wmma::accumulator, 16, 16, 16, float> c[4];
    #pragma unroll
    for (int nt = 0; nt < 4; nt++) wmma::fill_fragment(c[nt], 0.0f);
    const half* arow = As + warp * 16 * 64;
    #pragma unroll
    for (int k0 = 0; k0 < 64; k0 += 16) {
        wmma::fragment<wmma::matrix_a, 16, 16, 16, half, wmma::row_major> a;
        wmma::load_matrix_sync(a, arow + k0, 64);
        #pragma unroll
        for (int nt = 0; nt < 4; nt++) {
            wmma::fragment<wmma::matrix_b, 16, 16, 16, half, wmma::row_major> b;
            wmma::load_matrix_sync(b, Bs + k0 * 64 + nt * 16, 64);
            wmma::mma_sync(c[nt], a, b, c[nt]);
        }
    }
    __syncthreads();

    float* Cst = (float*)sraw + warp * 256;
    int r = lane >> 1;
    int chalf = (lane & 1) * 8;
    int grow = rowbase + warp * 16 + r;
    float di = (grow < NN) ? g_dinv[grow] : 0.f;
    #pragma unroll
    for (int nt = 0; nt < 4; nt++) {
        wmma::store_matrix_sync(Cst, c[nt], 16, wmma::mem_row_major);
        __syncwarp();
        if (grow < NN) {
            float4 v0 = *(const float4*)(Cst + r * 16 + chalf);
            float4 v1 = *(const float4*)(Cst + r * 16 + chalf + 4);
            __half2 h0 = __floats2half2_rn(di * v0.x, di * v0.y);
            __half2 h1 = __floats2half2_rn(di * v0.z, di * v0.w);
            __half2 h2 = __floats2half2_rn(di * v1.x, di * v1.y);
            __half2 h3 = __floats2half2_rn(di * v1.z, di * v1.w);
            *(uint4*)(out + (size_t)grow * 32 + nt * 8 + (lane & 1) * 4) =
                make_uint4(*(uint32_t*)&h0, *(uint32_t*)&h1,
                           *(uint32_t*)&h2, *(uint32_t*)&h3);
        }
        __syncwarp();
    }
}

// ---------------- Aggregation: warp-per-row (R5 form, 4-warp blocks) -------
// HALF_OUT: fp16 features out (intermediate); else fp32 (final output).
// ZERO_CNT: final layer restores g_cnt==0 invariant for next replay.
template<bool HALF_OUT, bool ZERO_CNT>
__global__ void k_agg(const __half2* __restrict__ h, const float* __restrict__ bias,
                      void* __restrict__ outv) {
    int wid  = (blockIdx.x * blockDim.x + threadIdx.x) >> 5;
    int lane = threadIdx.x & 31;
    if (wid >= NN) return;
    int start = g_rowptr[wid];
    int cnt   = g_cnt[wid];
    if (ZERO_CNT && lane == 0) g_cnt[wid] = 0;  // read precedes write in warp order
    float di  = g_dinv[wid];
    const int* cp = g_col + start;

    float a0 = 0.f, a1 = 0.f;
    int j = 0;
    for (; j + 8 <= cnt; j += 8) {
        int s0 = cp[j + 0], s1 = cp[j + 1], s2 = cp[j + 2], s3 = cp[j + 3];
        int s4 = cp[j + 4], s5 = cp[j + 5], s6 = cp[j + 6], s7 = cp[j + 7];
        __half2 v0 = h[s0 * 32 + lane];
        __half2 v1 = h[s1 * 32 + lane];
        __half2 v2 = h[s2 * 32 + lane];
        __half2 v3 = h[s3 * 32 + lane];
        __half2 v4 = h[s4 * 32 + lane];
        __half2 v5 = h[s5 * 32 + lane];
        __half2 v6 = h[s6 * 32 + lane];
        __half2 v7 = h[s7 * 32 + lane];
        float2 f0 = __half22float2(v0), f1 = __half22float2(v1);
        float2 f2 = __half22float2(v2), f3 = __half22float2(v3);
        float2 f4 = __half22float2(v4), f5 = __half22float2(v5);
        float2 f6 = __half22float2(v6), f7 = __half22float2(v7);
        a0 += f0.x + f1.x + f2.x + f3.x + f4.x + f5.x + f6.x + f7.x;
        a1 += f0.y + f1.y + f2.y + f3.y + f4.y + f5.y + f6.y + f7.y;
    }
    for (; j < cnt; j++) {
        int s = cp[j];
        float2 f = __half22float2(h[s * 32 + lane]);
        a0 += f.x; a1 += f.y;
    }

    float2 hs = __half22float2(h[wid * 32 + lane]);
    float2 bb = ((const float2*)bias)[lane];
    float o0 = di * (a0 + hs.x) + bb.x;
    float o1 = di * (a1 + hs.y) + bb.y;
    o0 = (o0 >= 0.f) ? o0 : NEG * o0;
    o1 = (o1 >= 0.f) ? o1 : NEG * o1;
    if (HALF_OUT) {
        ((__half2*)outv)[(size_t)wid * 32 + lane] = __floats2half2_rn(o0, o1);
    } else {
        float2 oo; oo.x = o0; oo.y = o1;
        ((float2*)outv)[(size_t)wid * 32 + lane] = oo;
    }
}

// ---------------- launch ----------------------------------------------------
extern "C" void kernel_launch(void* const* d_in, const int* in_sizes, int n_in,
                              void* d_out, int out_size) {
    (void)in_sizes; (void)n_in; (void)out_size;
    const float* x  = (const float*)d_in[0];
    const int*   ei = (const int*)d_in[1];
    const int* src = ei;
    const int* dst = ei + EE;
    const float* Wt[4] = { (const float*)d_in[2], (const float*)d_in[4],
                           (const float*)d_in[6], (const float*)d_in[8] };
    const float* bt[4] = { (const float*)d_in[3], (const float*)d_in[5],
                           (const float*)d_in[7], (const float*)d_in[9] };

    __half2 *p_h, *p_a, *p_b;
    cudaGetSymbolAddress((void**)&p_h, g_h);
    cudaGetSymbolAddress((void**)&p_a, g_bufA);
    cudaGetSymbolAddress((void**)&p_b, g_bufB);

    const int NB_SCAN = (NN + 1023) / 1024;    // 98
    const int NB_N256 = (NN + 255) / 256;      // 391
    const int NB_E4   = (EE / 4 + 255) / 256;  // 1563

    // CSR build — g_cnt==0 at entry (module init / restored by final k_agg)
    k_hist<<<NB_E4, 256>>>(dst);
    k_scanA<<<NB_SCAN, 1024>>>();
    k_scanB<<<1, 32>>>(NB_SCAN);
    k_scanC<<<NB_N256, 256>>>();
    k_scatter<<<NB_E4, 256>>>(src, dst);

    const int GEMM_BLOCKS = (NN + 127) / 128;  // 782
    const int AGG_BLOCKS  = (NN + 3) / 4;      // 25000 (128 thr, 4 warps/block)

    // layer 1
    k_gemm_wmma<true ><<<GEMM_BLOCKS, 256>>>(x,   Wt[0], p_h);
    k_agg<true , false><<<AGG_BLOCKS, 128>>>(p_h, bt[0], p_a);
    // layer 2
    k_gemm_wmma<false><<<GEMM_BLOCKS, 256>>>(p_a, Wt[1], p_h);
    k_agg<true , false><<<AGG_BLOCKS, 128>>>(p_h, bt[1], p_b);
    // layer 3
    k_gemm_wmma<false><<<GEMM_BLOCKS, 256>>>(p_b, Wt[2], p_h);
    k_agg<true , false><<<AGG_BLOCKS, 128>>>(p_h, bt[2], p_a);
    // layer 4 (final: fp32 out, restore g_cnt invariant)
    k_gemm_wmma<false><<<GEMM_BLOCKS, 256>>>(p_a, Wt[3], p_h);
    k_agg<false, true ><<<AGG_BLOCKS, 128>>>(p_h, bt[3], d_out);
}

// round 9
// speedup vs baseline: 1.5550x; 1.5014x over previous
#include <cuda_runtime.h>
#include <cuda_fp16.h>
#include <mma.h>
#include <math.h>
#include <stdint.h>

using namespace nvcuda;

#define NN 100000
#define EE 1600000
#define NEG 0.01f
#define COLCAP 2000000   // EE + 3*NN padding worst case, rounded up

// ---------------- scratch (device globals) ---------------------------------
// g_h has ONE extra row (index NN) that is never written: stays zero forever.
// Padded CSR entries point at it and contribute 0 to every aggregation.
__device__ __half2 g_h[(NN + 1) * 32];
__device__ __half2 g_bufA[NN * 32];  // fp16 node features (ping)
__device__ __half2 g_bufB[NN * 32];  // fp16 node features (pong)
__device__ int   g_cnt[NN];          // real in-degree (excl. self loop)
__device__ int   g_rowptr[NN];       // padded-CSR row starts (multiples of 4)
__device__ int   g_pos[NN];
__device__ int   g_col[COLCAP];
__device__ float g_dinv[NN];
__device__ int   g_bsum[128];

// ---------------- CSR build ------------------------------------------------
__global__ void k_zero_cnt() {
    int i = blockIdx.x * blockDim.x + threadIdx.x;
    if (i < NN) g_cnt[i] = 0;
}

__global__ void k_hist(const int* __restrict__ dst) {
    int t = blockIdx.x * blockDim.x + threadIdx.x;
    if (t * 4 < EE) {
        int4 d = ((const int4*)dst)[t];
        atomicAdd(&g_cnt[d.x], 1);
        atomicAdd(&g_cnt[d.y], 1);
        atomicAdd(&g_cnt[d.z], 1);
        atomicAdd(&g_cnt[d.w], 1);
    }
}

// scan PADDED counts (rounded to multiple of 4) so row starts are 16B aligned
__global__ void k_scanA() {
    __shared__ int s[1024];
    int tid = threadIdx.x;
    int i = blockIdx.x * 1024 + tid;
    int v = (i < NN) ? g_cnt[i] : 0;
    if (i < NN) g_dinv[i] = rsqrtf((float)(v + 1));
    int vp = (v + 3) & ~3;               // padded count
    s[tid] = vp;
    __syncthreads();
    #pragma unroll
    for (int off = 1; off < 1024; off <<= 1) {
        int t = (tid >= off) ? s[tid - off] : 0;
        __syncthreads();
        s[tid] += t;
        __syncthreads();
    }
    if (i < NN) g_rowptr[i] = s[tid] - vp;   // exclusive (padded) within block
    if (tid == 1023) g_bsum[blockIdx.x] = s[1023];
}

__global__ void k_scanB(int nb) {
    int lane = threadIdx.x;
    int base = lane * 4;
    int v0 = (base + 0 < nb) ? g_bsum[base + 0] : 0;
    int v1 = (base + 1 < nb) ? g_bsum[base + 1] : 0;
    int v2 = (base + 2 < nb) ? g_bsum[base + 2] : 0;
    int v3 = (base + 3 < nb) ? g_bsum[base + 3] : 0;
    int s1 = v0 + v1, s2 = s1 + v2, s3 = s2 + v3;
    int tot = s3;
    int run = tot;
    #pragma unroll
    for (int off = 1; off < 32; off <<= 1) {
        int t = __shfl_up_sync(0xffffffffu, run, off);
        if (lane >= off) run += t;
    }
    int excl = run - tot;
    if (base + 0 < nb) g_bsum[base + 0] = excl;
    if (base + 1 < nb) g_bsum[base + 1] = excl + v0;
    if (base + 2 < nb) g_bsum[base + 2] = excl + s1;
    if (base + 3 < nb) g_bsum[base + 3] = excl + s2;
}

// finalize rowptr, init scatter cursor, fill the <=3 pad slots with dummy NN
__global__ void k_scanC() {
    int i = blockIdx.x * blockDim.x + threadIdx.x;
    if (i < NN) {
        int rp = g_rowptr[i] + g_bsum[i >> 10];
        g_rowptr[i] = rp;
        g_pos[i] = rp;
        int cnt = g_cnt[i];
        int pad = (cnt + 3) & ~3;
        for (int k = cnt; k < pad; k++) g_col[rp + k] = NN;  // dummy -> zero row
    }
}

__global__ void k_scatter(const int* __restrict__ src, const int* __restrict__ dst) {
    int t = blockIdx.x * blockDim.x + threadIdx.x;
    if (t * 4 < EE) {
        int4 d = ((const int4*)dst)[t];
        int4 s = ((const int4*)src)[t];
        int p0 = atomicAdd(&g_pos[d.x], 1);
        int p1 = atomicAdd(&g_pos[d.y], 1);
        int p2 = atomicAdd(&g_pos[d.z], 1);
        int p3 = atomicAdd(&g_pos[d.w], 1);
        g_col[p0] = s.x;
        g_col[p1] = s.y;
        g_col[p2] = s.z;
        g_col[p3] = s.w;
    }
}

// ---------------- WMMA GEMM: h'[N,64](fp16) = dinv[row]*(in @ W) -----------
// 256 threads (8 warps), 128 rows/block. Each warp: 16-row strip, 4 n-tiles.
template<bool F32IN>
__global__ void __launch_bounds__(256) k_gemm_wmma(
    const void* __restrict__ inv, const float* __restrict__ W,
    __half2* __restrict__ out) {
    __shared__ __align__(16) char sraw[24576];
    half* As = (half*)sraw;             // 128 x 64 (ldm 64)
    half* Bs = (half*)(sraw + 16384);   // 64 x 64  (ldm 64)
    int tid  = threadIdx.x;
    int warp = tid >> 5, lane = tid & 31;
    int rowbase = blockIdx.x * 128;

    #pragma unroll
    for (int k = 0; k < 4; k++) {
        int i = tid + k * 256;
        float4 w = ((const float4*)W)[i];
        __half2 h0 = __floats2half2_rn(w.x, w.y);
        __half2 h1 = __floats2half2_rn(w.z, w.w);
        *(uint2*)(Bs + i * 4) = make_uint2(*(uint32_t*)&h0, *(uint32_t*)&h1);
    }
    if (F32IN) {
        const float4* in4 = (const float4*)inv;
        #pragma unroll
        for (int k = 0; k < 8; k++) {
            int i = tid + k * 256;
            int row = i >> 4, q = i & 15;
            int gr = rowbase + row;
            float4 v = (gr < NN) ? in4[(size_t)gr * 16 + q] : make_float4(0, 0, 0, 0);
            __half2 h0 = __floats2half2_rn(v.x, v.y);
            __half2 h1 = __floats2half2_rn(v.z, v.w);
            *(uint2*)(As + row * 64 + q * 4) =
                make_uint2(*(uint32_t*)&h0, *(uint32_t*)&h1);
        }
    } else {
        const uint4* in4 = (const uint4*)inv;
        #pragma unroll
        for (int k = 0; k < 4; k++) {
            int i = tid + k * 256;
            int row = i >> 3, q = i & 7;
            int gr = rowbase + row;
            uint4 v = (gr < NN) ? in4[(size_t)gr * 8 + q] : make_uint4(0, 0, 0, 0);
            *(uint4*)(As + row * 64 + q * 8) = v;
        }
    }
    __syncthreads();

    wmma::fragment<wmma::accumulator, 16, 16, 16, float> c[4];
    #pragma unroll
    for (int nt = 0; nt < 4; nt++) wmma::fill_fragment(c[nt], 0.0f);
    const half* arow = As + warp * 16 * 64;
    #pragma unroll
    for (int k0 = 0; k0 < 64; k0 += 16) {
        wmma::fragment<wmma::matrix_a, 16, 16, 16, half, wmma::row_major> a;
        wmma::load_matrix_sync(a, arow + k0, 64);
        #pragma unroll
        for (int nt = 0; nt < 4; nt++) {
            wmma::fragment<wmma::matrix_b, 16, 16, 16, half, wmma::row_major> b;
            wmma::load_matrix_sync(b, Bs + k0 * 64 + nt * 16, 64);
            wmma::mma_sync(c[nt], a, b, c[nt]);
        }
    }
    __syncthreads();

    float* Cst = (float*)sraw + warp * 256;
    int r = lane >> 1;
    int chalf = (lane & 1) * 8;
    int grow = rowbase + warp * 16 + r;
    float di = (grow < NN) ? g_dinv[grow] : 0.f;
    #pragma unroll
    for (int nt = 0; nt < 4; nt++) {
        wmma::store_matrix_sync(Cst, c[nt], 16, wmma::mem_row_major);
        __syncwarp();
        if (grow < NN) {
            float4 v0 = *(const float4*)(Cst + r * 16 + chalf);
            float4 v1 = *(const float4*)(Cst + r * 16 + chalf + 4);
            __half2 h0 = __floats2half2_rn(di * v0.x, di * v0.y);
            __half2 h1 = __floats2half2_rn(di * v0.z, di * v0.w);
            __half2 h2 = __floats2half2_rn(di * v1.x, di * v1.y);
            __half2 h3 = __floats2half2_rn(di * v1.z, di * v1.w);
            *(uint4*)(out + (size_t)grow * 32 + nt * 8 + (lane & 1) * 4) =
                make_uint4(*(uint32_t*)&h0, *(uint32_t*)&h1,
                           *(uint32_t*)&h2, *(uint32_t*)&h3);
        }
        __syncwarp();
    }
}

// ---------------- Aggregation: warp-per-row, int4 index loads --------------
// Row is padded to a multiple of 4 with dummy index NN (zero row): no tail.
template<bool HALF_OUT>
__global__ void k_agg(const __half2* __restrict__ h, const float* __restrict__ bias,
                      void* __restrict__ outv) {
    int wid  = (blockIdx.x * blockDim.x + threadIdx.x) >> 5;
    int lane = threadIdx.x & 31;
    if (wid >= NN) return;
    int start = g_rowptr[wid];          // multiple of 4 -> cp is 16B aligned
    int cnt   = g_cnt[wid];
    float di  = g_dinv[wid];
    const int* cp = g_col + start;
    int cntp = (cnt + 3) & ~3;

    float a0 = 0.f, a1 = 0.f;
    int j = 0;
    for (; j + 8 <= cntp; j += 8) {
        int4 sa = *(const int4*)(cp + j);
        int4 sb = *(const int4*)(cp + j + 4);
        __half2 v0 = h[sa.x * 32 + lane];
        __half2 v1 = h[sa.y * 32 + lane];
        __half2 v2 = h[sa.z * 32 + lane];
        __half2 v3 = h[sa.w * 32 + lane];
        __half2 v4 = h[sb.x * 32 + lane];
        __half2 v5 = h[sb.y * 32 + lane];
        __half2 v6 = h[sb.z * 32 + lane];
        __half2 v7 = h[sb.w * 32 + lane];
        float2 f0 = __half22float2(v0), f1 = __half22float2(v1);
        float2 f2 = __half22float2(v2), f3 = __half22float2(v3);
        float2 f4 = __half22float2(v4), f5 = __half22float2(v5);
        float2 f6 = __half22float2(v6), f7 = __half22float2(v7);
        a0 += f0.x + f1.x + f2.x + f3.x + f4.x + f5.x + f6.x + f7.x;
        a1 += f0.y + f1.y + f2.y + f3.y + f4.y + f5.y + f6.y + f7.y;
    }
    if (j < cntp) {                     // at most one remaining int4 group
        int4 sa = *(const int4*)(cp + j);
        __half2 v0 = h[sa.x * 32 + lane];
        __half2 v1 = h[sa.y * 32 + lane];
        __half2 v2 = h[sa.z * 32 + lane];
        __half2 v3 = h[sa.w * 32 + lane];
        float2 f0 = __half22float2(v0), f1 = __half22float2(v1);
        float2 f2 = __half22float2(v2), f3 = __half22float2(v3);
        a0 += f0.x + f1.x + f2.x + f3.x;
        a1 += f0.y + f1.y + f2.y + f3.y;
    }

    float2 hs = __half22float2(h[wid * 32 + lane]);
    float2 bb = ((const float2*)bias)[lane];
    float o0 = di * (a0 + hs.x) + bb.x;
    float o1 = di * (a1 + hs.y) + bb.y;
    o0 = (o0 >= 0.f) ? o0 : NEG * o0;
    o1 = (o1 >= 0.f) ? o1 : NEG * o1;
    if (HALF_OUT) {
        ((__half2*)outv)[(size_t)wid * 32 + lane] = __floats2half2_rn(o0, o1);
    } else {
        float2 oo; oo.x = o0; oo.y = o1;
        ((float2*)outv)[(size_t)wid * 32 + lane] = oo;
    }
}

// ---------------- launch ----------------------------------------------------
extern "C" void kernel_launch(void* const* d_in, const int* in_sizes, int n_in,
                              void* d_out, int out_size) {
    (void)in_sizes; (void)n_in; (void)out_size;
    const float* x  = (const float*)d_in[0];
    const int*   ei = (const int*)d_in[1];
    const int* src = ei;
    const int* dst = ei + EE;
    const float* Wt[4] = { (const float*)d_in[2], (const float*)d_in[4],
                           (const float*)d_in[6], (const float*)d_in[8] };
    const float* bt[4] = { (const float*)d_in[3], (const float*)d_in[5],
                           (const float*)d_in[7], (const float*)d_in[9] };

    __half2 *p_h, *p_a, *p_b;
    cudaGetSymbolAddress((void**)&p_h, g_h);
    cudaGetSymbolAddress((void**)&p_a, g_bufA);
    cudaGetSymbolAddress((void**)&p_b, g_bufB);

    const int NB_SCAN = (NN + 1023) / 1024;    // 98
    const int NB_N256 = (NN + 255) / 256;      // 391
    const int NB_E4   = (EE / 4 + 255) / 256;  // 1563

    // CSR build (edge-structure only; shared by all 4 layers)
    k_zero_cnt<<<NB_N256, 256>>>();
    k_hist<<<NB_E4, 256>>>(dst);
    k_scanA<<<NB_SCAN, 1024>>>();
    k_scanB<<<1, 32>>>(NB_SCAN);
    k_scanC<<<NB_N256, 256>>>();
    k_scatter<<<NB_E4, 256>>>(src, dst);

    const int GEMM_BLOCKS = (NN + 127) / 128;  // 782
    const int AGG_BLOCKS  = NN / 8;            // 12500 (8 warps/block)

    // layer 1
    k_gemm_wmma<true ><<<GEMM_BLOCKS, 256>>>(x,   Wt[0], p_h);
    k_agg<true ><<<AGG_BLOCKS, 256>>>(p_h, bt[0], p_a);
    // layer 2
    k_gemm_wmma<false><<<GEMM_BLOCKS, 256>>>(p_a, Wt[1], p_h);
    k_agg<true ><<<AGG_BLOCKS, 256>>>(p_h, bt[1], p_b);
    // layer 3
    k_gemm_wmma<false><<<GEMM_BLOCKS, 256>>>(p_b, Wt[2], p_h);
    k_agg<true ><<<AGG_BLOCKS, 256>>>(p_h, bt[2], p_a);
    // layer 4
    k_gemm_wmma<false><<<GEMM_BLOCKS, 256>>>(p_a, Wt[3], p_h);
    k_agg<false><<<AGG_BLOCKS, 256>>>(p_h, bt[3], d_out);
}